// round 12
// baseline (speedup 1.0000x reference)
#include <cuda_runtime.h>
#include <math.h>

#define BB 4
#define SS 4096
#define DD 1024
#define ND 4096                   // floats per (b,s)
#define ND4 1024                  // float4 per (b,s)
#define D4 256                    // float4 per stream row
#define NCOLS 24
#define SCHUNKS 32
#define SPERCHUNK 128
#define GA 16                     // gate col-blocks per batch (64 total)

// Scratch (allocation-free rule: __device__ globals)
__device__ float    g_partial[BB][SCHUNKS][ND];    // 2 MB
__device__ float    g_dpart[BB][GA][NCOLS];
__device__ float    g_ssp[BB][GA];
__device__ float    g_gates[BB][24];               // pre[4], post[4], P[16]
__device__ unsigned g_gcnt;                        // gate completion counter

// ---------------------------------------------------------------------------
// Kernel 1: column partial sums over S, per 128-row chunk, s DESCENDING so the
// head half of every chunk is L2-resident at kernel end (consumed first by the
// hot half of k_mix). Evict-normal loads. grid (4, 32, 4) x 256.
// ---------------------------------------------------------------------------
__global__ void __launch_bounds__(256) k_reduce(const float4* __restrict__ H4) {
    const int b     = blockIdx.z;
    const int chunk = blockIdx.y;
    const int col4  = blockIdx.x * 256 + threadIdx.x;
    const float4* base = H4 + ((size_t)b * SS + (size_t)chunk * SPERCHUNK) * ND4 + col4;
    float4 acc = make_float4(0.f, 0.f, 0.f, 0.f);
#pragma unroll 16
    for (int s = SPERCHUNK - 1; s >= 0; s--) {
        const float4 v = base[(size_t)s * ND4];
        acc.x += v.x; acc.y += v.y; acc.z += v.z; acc.w += v.w;
    }
    ((float4*)&g_partial[b][chunk][0])[col4] = acc;
}

// ---------------------------------------------------------------------------
// Kernel 2: fused gate reduction + finalize. 64 blocks x 256 threads; the
// LAST block to finish (order-independent result) runs sigmoid/Sinkhorn.
// ---------------------------------------------------------------------------
__global__ void __launch_bounds__(256) k_gates(const float* __restrict__ phi,
                                               const float* __restrict__ pre_base,
                                               const float* __restrict__ post_base,
                                               const float* __restrict__ res_base,
                                               const float* __restrict__ a_pre,
                                               const float* __restrict__ a_post,
                                               const float* __restrict__ a_res) {
    const int b    = blockIdx.x >> 4;
    const int g    = blockIdx.x & 15;
    const int t    = threadIdx.x;
    const int lane = t & 31;
    const int warp = t >> 5;                 // 0..7
    const int col  = g * 256 + t;

    float x = 0.0f;
#pragma unroll
    for (int ch = 0; ch < SCHUNKS; ch++) x += g_partial[b][ch][col];
    x *= (1.0f / (float)SS);

    float acc24[NCOLS];
    const float* ph = phi + (size_t)col * NCOLS;
#pragma unroll
    for (int j = 0; j < NCOLS; j++) acc24[j] = x * ph[j];
    float ss = x * x;

#pragma unroll
    for (int o = 16; o > 0; o >>= 1) {
        ss += __shfl_down_sync(0xffffffffu, ss, o);
#pragma unroll
        for (int j = 0; j < NCOLS; j++)
            acc24[j] += __shfl_down_sync(0xffffffffu, acc24[j], o);
    }

    __shared__ float sred[8][NCOLS];
    __shared__ float sss[8];
    if (lane == 0) {
#pragma unroll
        for (int j = 0; j < NCOLS; j++) sred[warp][j] = acc24[j];
        sss[warp] = ss;
    }
    __syncthreads();

    if (t < NCOLS) {
        float v = 0.0f;
#pragma unroll
        for (int w = 0; w < 8; w++) v += sred[w][t];
        g_dpart[b][g][t] = v;
    } else if (t == NCOLS) {
        float v = 0.0f;
#pragma unroll
        for (int w = 0; w < 8; w++) v += sss[w];
        g_ssp[b][g] = v;
    }
    if (t <= NCOLS) __threadfence();
    __syncthreads();

    __shared__ int is_last;
    if (t == 0) {
        const unsigned old = atomicAdd(&g_gcnt, 1u);
        is_last = (old == (unsigned)(BB * GA - 1));
        if (is_last) atomicExch(&g_gcnt, 0u);    // self-reset for graph replay
        if (is_last) __threadfence();
    }
    __syncthreads();
    if (!is_last) return;

    if (t < 128) {
        const int bb = t >> 5;
        const int ln = t & 31;

        __shared__ float sdelta[BB][NCOLS];

        float invrms = 0.0f;
        if (ln == 0) {
            float ssum = 0.0f;
#pragma unroll
            for (int k = 0; k < GA; k++) ssum += g_ssp[bb][k];
            invrms = 1.0f / sqrtf(ssum * (1.0f / (float)ND) + 1e-6f);
        }
        invrms = __shfl_sync(0xffffffffu, invrms, 0);

        if (ln < NCOLS) {
            float v = 0.0f;
#pragma unroll
            for (int k = 0; k < GA; k++) v += g_dpart[bb][k][ln];
            sdelta[bb][ln] = v * invrms;
        }
        __syncwarp();

        if (ln == 0) {
            const float ap  = *a_pre;
            const float apo = *a_post;
            const float ar  = *a_res;

            float pre[4];
            float psum = 0.0f;
#pragma unroll
            for (int k = 0; k < 4; k++) {
                pre[k] = 1.0f / (1.0f + expf(-(pre_base[k] + ap * sdelta[bb][k])));
                psum += pre[k];
            }
            const float pinv = 1.0f / (psum + 1e-8f);
#pragma unroll
            for (int k = 0; k < 4; k++) g_gates[bb][k] = pre[k] * pinv;

#pragma unroll
            for (int k = 0; k < 4; k++)
                g_gates[bb][4 + k] =
                    1.0f / (1.0f + expf(-(post_base[k] + apo * sdelta[bb][4 + k])));

            float P[16];
#pragma unroll
            for (int q = 0; q < 16; q++)
                P[q] = expf(res_base[q] + ar * sdelta[bb][8 + q]);
            for (int it = 0; it < 20; it++) {
#pragma unroll
                for (int i = 0; i < 4; i++) {
                    const float rs = P[i*4+0] + P[i*4+1] + P[i*4+2] + P[i*4+3];
                    const float inv = 1.0f / (rs + 1e-6f);
                    P[i*4+0] *= inv; P[i*4+1] *= inv; P[i*4+2] *= inv; P[i*4+3] *= inv;
                }
#pragma unroll
                for (int j = 0; j < 4; j++) {
                    const float cs = P[0*4+j] + P[1*4+j] + P[2*4+j] + P[3*4+j];
                    const float inv = 1.0f / (cs + 1e-6f);
                    P[0*4+j] *= inv; P[1*4+j] *= inv; P[2*4+j] *= inv; P[3*4+j] *= inv;
                }
            }
#pragma unroll
            for (int q = 0; q < 16; q++) g_gates[bb][8 + q] = P[q];
        }
    }
}

// ---------------------------------------------------------------------------
// Kernel 3: streaming mix, FOUR rows per block (20 independent .cs float4
// loads in flight per thread before any store). Hot halves at low blockIdx.
// grid 4096 x 256; __launch_bounds__(256,2) caps regs at 128.
// ---------------------------------------------------------------------------
__global__ void __launch_bounds__(256, 2) k_mix(const float* __restrict__ H,
                                                const float* __restrict__ bo,
                                                float* __restrict__ out) {
    const int idx   = blockIdx.x;            // 0..4095
    const int half  = idx >> 11;             // 0 = hot halves, 1 = cold
    const int rest  = idx & 2047;
    const int grp   = rest & 15;             // 16 groups of 4 rows per half
    const int chunk = (rest >> 4) & 31;
    const int b     = rest >> 9;
    const int bs    = b * SS + chunk * SPERCHUNK + half * 64 + grp * 4;
    const int d4    = threadIdx.x;

    __shared__ float g[24];
    if (threadIdx.x < 24) g[threadIdx.x] = g_gates[b][threadIdx.x];

    // All 20 loads issued before the sync: maximal MLP, overlaps gate wait.
    float4 h[4][4];
    float4 bv[4];
#pragma unroll
    for (int r = 0; r < 4; r++) {
        const float4* hp = (const float4*)(H + (size_t)(bs + r) * ND);
#pragma unroll
        for (int k = 0; k < 4; k++) h[r][k] = __ldcs(hp + k * D4 + d4);
        bv[r] = __ldcs((const float4*)(bo + (size_t)(bs + r) * DD) + d4);
    }

    __syncthreads();

#pragma unroll
    for (int r = 0; r < 4; r++) {
        float4* ob = (float4*)(out + (size_t)(bs + r) * 5 * DD);

        float4 o;
        o.x = g[0]*h[r][0].x + g[1]*h[r][1].x + g[2]*h[r][2].x + g[3]*h[r][3].x;
        o.y = g[0]*h[r][0].y + g[1]*h[r][1].y + g[2]*h[r][2].y + g[3]*h[r][3].y;
        o.z = g[0]*h[r][0].z + g[1]*h[r][1].z + g[2]*h[r][2].z + g[3]*h[r][3].z;
        o.w = g[0]*h[r][0].w + g[1]*h[r][1].w + g[2]*h[r][2].w + g[3]*h[r][3].w;
        __stcs(ob + d4, o);

#pragma unroll
        for (int i = 0; i < 4; i++) {
            const float r0 = g[8 + i * 4 + 0];
            const float r1 = g[8 + i * 4 + 1];
            const float r2 = g[8 + i * 4 + 2];
            const float r3 = g[8 + i * 4 + 3];
            const float p  = g[4 + i];
            float4 u;
            u.x = r0*h[r][0].x + r1*h[r][1].x + r2*h[r][2].x + r3*h[r][3].x + p*bv[r].x;
            u.y = r0*h[r][0].y + r1*h[r][1].y + r2*h[r][2].y + r3*h[r][3].y + p*bv[r].y;
            u.z = r0*h[r][0].z + r1*h[r][1].z + r2*h[r][2].z + r3*h[r][3].z + p*bv[r].z;
            u.w = r0*h[r][0].w + r1*h[r][1].w + r2*h[r][2].w + r3*h[r][3].w + p*bv[r].w;
            __stcs(ob + (1 + i) * D4 + d4, u);
        }
    }
}

// ---------------------------------------------------------------------------
extern "C" void kernel_launch(void* const* d_in, const int* in_sizes, int n_in,
                              void* d_out, int out_size) {
    const float* H         = (const float*)d_in[0];
    const float* branch_o  = (const float*)d_in[1];
    const float* phi       = (const float*)d_in[2];
    const float* pre_base  = (const float*)d_in[3];
    const float* post_base = (const float*)d_in[4];
    const float* res_base  = (const float*)d_in[5];
    const float* a_pre     = (const float*)d_in[6];
    const float* a_post    = (const float*)d_in[7];
    const float* a_res     = (const float*)d_in[8];
    float* out = (float*)d_out;

    dim3 g1(ND4 / 256, SCHUNKS, BB);
    k_reduce<<<g1, 256>>>((const float4*)H);
    k_gates<<<BB * GA, 256>>>(phi, pre_base, post_base, res_base,
                              a_pre, a_post, a_res);
    const int mix_grid = (BB * SS) / 4;       // 4096 blocks, 4 rows each
    k_mix<<<mix_grid, 256>>>(H, branch_o, out);
}